// round 13
// baseline (speedup 1.0000x reference)
#include <cuda_runtime.h>
#include <cuda_bf16.h>
#include <stdint.h>
#include <math.h>

// Problem constants
#define BB 8
#define NN 100000
#define MM 2048
#define KK 32
#define DD 128
#define IC 132
#define EPSV 1e-5f

// word strides (32-bit words; each word = 2 bf16 along K)
#define STRX 76
#define STRW1 76
#define STRW2 68

// smem word-offset layout
#define XS_W   0                 // 16 warps * 32 rows * 76 words = 38912
#define W1T_W  38912             // 128 * 76 = 9728
#define W2T_W  48640             // 128 * 68 = 8704
#define B1_W   57344             // 128
#define B2_W   57472             // 128
#define LNG_W  57600             // 128
#define LNB_W  57728             // 128
#define FLAG_W 57856             // 4
#define SMEM_WORDS 57860
#define SMEM_BYTES (SMEM_WORDS * 4)   // 231,440 B

#define XS_WARP_W 2432           // 32 * 76

// FiLM table in device global (L2-hot)
__device__ float g_film[BB * 2 * DD];

__device__ __forceinline__ float silu_f(float v) {
    return v * (1.0f / (1.0f + __expf(-v)));
}
__device__ __forceinline__ unsigned pkbf(float lo, float hi) {
    unsigned r;
    asm("cvt.rn.bf16x2.f32 %0, %1, %2;" : "=r"(r) : "f"(hi), "f"(lo));
    return r;
}
__device__ __forceinline__ void mma_bf16(float d[4],
                                         unsigned a0, unsigned a1,
                                         unsigned a2, unsigned a3,
                                         unsigned b0, unsigned b1) {
    asm volatile(
        "mma.sync.aligned.m16n8k16.row.col.f32.bf16.bf16.f32 "
        "{%0,%1,%2,%3}, {%4,%5,%6,%7}, {%8,%9}, {%0,%1,%2,%3};\n"
        : "+f"(d[0]), "+f"(d[1]), "+f"(d[2]), "+f"(d[3])
        : "r"(a0), "r"(a1), "r"(a2), "r"(a3), "r"(b0), "r"(b1));
}
__device__ __forceinline__ void ldsm4(unsigned& r0, unsigned& r1,
                                      unsigned& r2, unsigned& r3, unsigned a) {
    asm volatile("ldmatrix.sync.aligned.m8n8.x4.shared.b16 {%0,%1,%2,%3}, [%4];"
                 : "=r"(r0), "=r"(r1), "=r"(r2), "=r"(r3) : "r"(a));
}
__device__ __forceinline__ unsigned smem_u32(const void* p) {
    unsigned a;
    asm("{ .reg .u64 t; cvta.to.shared.u64 t, %1; cvt.u32.u64 %0, t; }"
        : "=r"(a) : "l"(p));
    return a;
}

// full gather (xyz + features) for one supernode into warp-private xs.
// Writes words 0..65 of rows < V (66..71 stay zero, 72..75 untouched).
// Feature batches of 4 rows (MLP=4) to keep register pressure low.
__device__ __forceinline__ void gather_su(unsigned* xsw,
                                          const float* __restrict__ point_feat,
                                          const float* __restrict__ point_xyz,
                                          const float* __restrict__ sup_xyz,
                                          int s, int b, unsigned bal, int V,
                                          int nid_k, int lane)
{
    const float* pf = point_feat + (size_t)b * NN * DD;
    // xyz: lane r handles row r (parallel across lanes)
    {
        const unsigned srcx = (lane < V) ? __fns(bal, 0, lane + 1) : 0u;
        const int nidx_l = __shfl_sync(0xffffffffu, nid_k, srcx);
        if (lane < V) {
            const float* px = point_xyz + (size_t)b * NN * 3;
            float rx  = px[nidx_l * 3 + 0] - sup_xyz[s * 3 + 0];
            float ryv = px[nidx_l * 3 + 1] - sup_xyz[s * 3 + 1];
            float rz  = px[nidx_l * 3 + 2] - sup_xyz[s * 3 + 2];
            float dd  = sqrtf(rx * rx + ryv * ryv + rz * rz);
            *(uint2*)(xsw + lane * STRX + 64) =
                make_uint2(pkbf(rx, ryv), pkbf(rz, dd));
        }
    }
    // features: batches of 4 rows, MLP=4
#pragma unroll
    for (int b4 = 0; b4 < 8; ++b4) {
        const int r0 = b4 * 4;
        if (r0 >= V) break;
        float4 f[4];
#pragma unroll
        for (int j = 0; j < 4; ++j) {
            const int r = r0 + j;
            const bool val = r < V;
            const unsigned src = val ? __fns(bal, 0, r + 1) : 0u;
            const int nid = __shfl_sync(0xffffffffu, nid_k, src);
            if (val)
                f[j] = *(const float4*)(pf + (size_t)nid * DD + 4 * lane);
        }
#pragma unroll
        for (int j = 0; j < 4; ++j) {
            const int r = r0 + j;
            if (r < V)
                *(uint2*)(xsw + r * STRX + 2 * lane) =
                    make_uint2(pkbf(f[j].x, f[j].y), pkbf(f[j].z, f[j].w));
        }
    }
    __syncwarp();
}

extern __shared__ unsigned usm[];

__global__ __launch_bounds__(512, 1)
void msg_kernel(const float* __restrict__ point_feat,
                const float* __restrict__ point_xyz,
                const float* __restrict__ sup_xyz,
                const int*   __restrict__ nidx,
                const void*  __restrict__ nmask,
                const float* __restrict__ init_feat,
                const float* __restrict__ task_emb,
                const float* __restrict__ W1, const float* __restrict__ b1,
                const float* __restrict__ W2, const float* __restrict__ b2,
                const float* __restrict__ Wf, const float* __restrict__ bf,
                const float* __restrict__ ln_g, const float* __restrict__ ln_b,
                float* __restrict__ out)
{
    float* b1s  = (float*)(usm + B1_W);
    float* b2s  = (float*)(usm + B2_W);
    float* lngs = (float*)(usm + LNG_W);
    float* lnbs = (float*)(usm + LNB_W);
    int*   flag = (int*)(usm + FLAG_W);

    const int tid = threadIdx.x;

    // ---- prologue: mask dtype detect ----
    if (tid == 0) *flag = 0;
    __syncthreads();
    {
        bool big = false;
        const unsigned* mw = (const unsigned*)nmask;
        for (int i = tid; i < 2048; i += 512)
            if (mw[i] > 1u) big = true;
        if (big) atomicOr(flag, 1);
    }
    // ---- FiLM table -> device global ----
    for (int p = 0; p < 4; ++p) {
        const int bb = p * 2 + (tid >> 8);
        const int j  = tid & 255;
        float acc = bf[j];
        const float* te = task_emb + bb * DD;
#pragma unroll 8
        for (int d = 0; d < DD; ++d)
            acc += te[d] * Wf[d * (2 * DD) + j];
        g_film[bb * 256 + j] = acc;
    }
    // ---- stage W1^T ----
    for (int i = tid; i < DD * STRW1; i += 512) {
        int col = i % DD, kw = i / DD;
        int k0 = 2 * kw, k1 = 2 * kw + 1;
        float v0 = (k0 < IC) ? W1[k0 * DD + col] : 0.f;
        float v1 = (k1 < IC) ? W1[k1 * DD + col] : 0.f;
        usm[W1T_W + col * STRW1 + kw] = pkbf(v0, v1);
    }
    // ---- stage W2^T ----
    for (int i = tid; i < DD * STRW2; i += 512) {
        int col = i % DD, kw = i / DD;
        int k0 = 2 * kw, k1 = 2 * kw + 1;
        float v0 = (k0 < DD) ? W2[k0 * DD + col] : 0.f;
        float v1 = (k1 < DD) ? W2[k1 * DD + col] : 0.f;
        usm[W2T_W + col * STRW2 + kw] = pkbf(v0, v1);
    }
    // ---- zero xs pad words 66..71 (k 132..143) ----
    for (int i = tid; i < 16 * 32 * 6; i += 512) {
        int w_ = i / 192, rem = i % 192;
        int row = rem / 6, pw = 66 + rem % 6;
        usm[XS_W + w_ * XS_WARP_W + row * STRX + pw] = 0u;
    }
    // ---- small vectors ----
    for (int i = tid; i < DD; i += 512) {
        b1s[i] = b1[i]; b2s[i] = b2[i]; lngs[i] = ln_g[i]; lnbs[i] = ln_b[i];
    }
    __syncthreads();
    const int mask_u8 = *flag;

    const int wid  = tid >> 5;
    const int lane = tid & 31;
    const int q    = lane & 3;
    const int g    = lane >> 2;

    unsigned* xsw = usm + XS_W + wid * XS_WARP_W;

    const unsigned sbase = smem_u32(usm);
    const int rowA = lane & 15, halfA = lane >> 4;
    const unsigned axA0 = sbase + 4u * (XS_W + wid * XS_WARP_W + rowA * STRX + halfA * 4);
    const int rB = lane & 7, tB = (lane >> 4) & 1, hB = (lane >> 3) & 1;
    const unsigned awB1 = sbase + 4u * (W1T_W + (tB * 8 + rB) * STRW1 + hB * 4);
    const unsigned awB2 = sbase + 4u * (W2T_W + (tB * 8 + rB) * STRW2 + hB * 4);

    const int TOT = BB * MM;
    const int sstep = gridDim.x * 16;

    int s = blockIdx.x * 16 + wid;
    unsigned bal = 0; int V = 0;

    // ---- software-pipeline prologue: gather first supernode ----
    if (s < TOT) {
        const size_t kb = (size_t)s * KK + lane;
        const int nid_k = nidx[kb];
        bool mk;
        if (mask_u8) mk = ((const uint8_t*)nmask)[kb] != 0;
        else         mk = ((const int*)nmask)[kb] != 0;
        bal = __ballot_sync(0xffffffffu, mk);
        V = __popc(bal);
        gather_su(xsw, point_feat, point_xyz, sup_xyz, s, s >> 11, bal, V,
                  nid_k, lane);
    }

    for (; s < TOT; s += sstep) {
        const int b = s >> 11;
        const int sn = s + sstep;
        const bool have = sn < TOT;

        // prefetch next supernode's indices + mask
        int nidk_n = 0; bool mk_n = false;
        if (have) {
            const size_t kbn = (size_t)sn * KK + lane;
            nidk_n = nidx[kbn];
            if (mask_u8) mk_n = ((const uint8_t*)nmask)[kbn] != 0;
            else         mk_n = ((const int*)nmask)[kbn] != 0;
        }

        const int ntl = (V > 16) ? 2 : 1;

        // ---- GEMM1: nb outer, tl inner -> per-nb masked row-sums -> hpk ----
        unsigned hpk[4][4];
#pragma unroll
        for (int nb = 0; nb < 4; ++nb) {
            float hs[4][2];
#pragma unroll
            for (int t = 0; t < 4; ++t) { hs[t][0] = 0.f; hs[t][1] = 0.f; }

            for (int tl = 0; tl < ntl; ++tl) {
                const bool v0 = (tl * 16 + g)     < V;
                const bool v1 = (tl * 16 + g + 8) < V;
                float acc[4][4];
#pragma unroll
                for (int t = 0; t < 4; ++t)
                    acc[t][0] = acc[t][1] = acc[t][2] = acc[t][3] = 0.f;
                unsigned aA = axA0 + (unsigned)tl * 4864u;   // +16*STRX*4
                unsigned aB = awB1 + nb * 9728u;             // +32*STRW1*4
#pragma unroll
                for (int kk = 0; kk < 9; ++kk) {
                    unsigned A0, A1, A2, A3, B0, B1, B2, B3, B4, B5, B6, B7;
                    ldsm4(A0, A1, A2, A3, aA);
                    ldsm4(B0, B1, B2, B3, aB);
                    ldsm4(B4, B5, B6, B7, aB + 4864u);       // +16*STRW1*4
                    mma_bf16(acc[0], A0, A1, A2, A3, B0, B1);
                    mma_bf16(acc[1], A0, A1, A2, A3, B2, B3);
                    mma_bf16(acc[2], A0, A1, A2, A3, B4, B5);
                    mma_bf16(acc[3], A0, A1, A2, A3, B6, B7);
                    aA += 32u; aB += 32u;
                }
                // bias + f32 silu + masked accumulate into row-sum
#pragma unroll
                for (int t = 0; t < 4; ++t) {
                    float2 bv = *(const float2*)(b1s + nb * 32 + t * 8 + 2 * q);
                    float s0 = silu_f(acc[t][0] + bv.x);
                    float s1 = silu_f(acc[t][1] + bv.y);
                    float s2 = silu_f(acc[t][2] + bv.x);
                    float s3 = silu_f(acc[t][3] + bv.y);
                    hs[t][0] += (v0 ? s0 : 0.f) + (v1 ? s2 : 0.f);
                    hs[t][1] += (v0 ? s1 : 0.f) + (v1 ? s3 : 0.f);
                }
            }
            // butterfly reduce over g-lanes + pack (per nb)
#pragma unroll
            for (int t = 0; t < 4; ++t) {
#pragma unroll
                for (int off = 4; off <= 16; off <<= 1) {
                    hs[t][0] += __shfl_xor_sync(0xffffffffu, hs[t][0], off);
                    hs[t][1] += __shfl_xor_sync(0xffffffffu, hs[t][1], off);
                }
                hpk[nb][t] = pkbf(hs[t][0], hs[t][1]);
            }
        }

        // ---- xs k-words now dead: gather next supernode (hidden by GEMM2) ----
        unsigned bal_n = 0; int V_n = 0;
        if (have) {
            bal_n = __ballot_sync(0xffffffffu, mk_n);
            V_n = __popc(bal_n);
            gather_su(xsw, point_feat, point_xyz, sup_xyz, sn, sn >> 11,
                      bal_n, V_n, nidk_n, lane);
        }
        // prefetch epilogue residual input (covered by GEMM2)
        float4 fi = *(const float4*)(init_feat + (size_t)s * DD + 4 * lane);

        // ---- GEMM2: msg_sum = hsum @ W2, single m16 tile, row 0 only ----
        const bool g0 = (g == 0);
        for (int nb2 = 0; nb2 < 4; ++nb2) {
            float facc[4][4];
#pragma unroll
            for (int t = 0; t < 4; ++t)
                facc[t][0] = facc[t][1] = facc[t][2] = facc[t][3] = 0.f;
            unsigned aB = awB2 + nb2 * 8704u;                // +32*STRW2*4
#pragma unroll
            for (int kk = 0; kk < 8; ++kk) {
                unsigned B0, B1, B2, B3, B4, B5, B6, B7;
                ldsm4(B0, B1, B2, B3, aB);
                ldsm4(B4, B5, B6, B7, aB + 4352u);           // +16*STRW2*4
                const unsigned a0 = g0 ? hpk[kk >> 1][2 * (kk & 1)] : 0u;
                const unsigned a2 = g0 ? hpk[kk >> 1][2 * (kk & 1) + 1] : 0u;
                mma_bf16(facc[0], a0, 0u, a2, 0u, B0, B1);
                mma_bf16(facc[1], a0, 0u, a2, 0u, B2, B3);
                mma_bf16(facc[2], a0, 0u, a2, 0u, B4, B5);
                mma_bf16(facc[3], a0, 0u, a2, 0u, B6, B7);
                aB += 32u;
            }
            // row 0 of D = msg_sum, held by lanes g==0 — no reduce needed
            if (lane < 4) {
#pragma unroll
                for (int t = 0; t < 4; ++t) {
                    const int c = nb2 * 32 + t * 8 + 2 * q;
                    *(float2*)(xsw + (c >> 2) * STRX + 72 + (c & 3)) =
                        make_float2(facc[t][0], facc[t][1]);
                }
            }
        }
        __syncwarp();

        // ---- epilogue: mean(+V*b2), FiLM, residual, LayerNorm ----
        {
            float4 msg = *(float4*)(xsw + lane * STRX + 72);
            const float Vf = (float)V;
            const float invV = 1.0f / fmaxf(Vf, 1.0f);
            float4 b2v = *(const float4*)(b2s + 4 * lane);
            float4 gm  = *(const float4*)(g_film + b * 256 + 4 * lane);
            float4 bt  = *(const float4*)(g_film + b * 256 + 128 + 4 * lane);
            float h0 = fi.x + ((msg.x + Vf * b2v.x) * invV) * (1.0f + gm.x) + bt.x;
            float h1 = fi.y + ((msg.y + Vf * b2v.y) * invV) * (1.0f + gm.y) + bt.y;
            float h2 = fi.z + ((msg.z + Vf * b2v.z) * invV) * (1.0f + gm.z) + bt.z;
            float h3 = fi.w + ((msg.w + Vf * b2v.w) * invV) * (1.0f + gm.w) + bt.w;
            float sum = h0 + h1 + h2 + h3;
            float sq  = h0 * h0 + h1 * h1 + h2 * h2 + h3 * h3;
#pragma unroll
            for (int off = 16; off; off >>= 1) {
                sum += __shfl_xor_sync(0xffffffffu, sum, off);
                sq  += __shfl_xor_sync(0xffffffffu, sq,  off);
            }
            const float mu  = sum * (1.0f / DD);
            const float var = sq * (1.0f / DD) - mu * mu;
            const float rs  = rsqrtf(var + EPSV);
            float4 lg = *(const float4*)(lngs + 4 * lane);
            float4 lb = *(const float4*)(lnbs + 4 * lane);
            float4 y;
            y.x = (h0 - mu) * rs * lg.x + lb.x;
            y.y = (h1 - mu) * rs * lg.y + lb.y;
            y.z = (h2 - mu) * rs * lg.z + lb.z;
            y.w = (h3 - mu) * rs * lg.w + lb.w;
            *(float4*)(out + (size_t)s * DD + 4 * lane) = y;
        }

        // rotate pipeline state
        bal = bal_n; V = V_n;
    }
}

// ---------------------------------------------------------------------------
extern "C" void kernel_launch(void* const* d_in, const int* in_sizes, int n_in,
                              void* d_out, int out_size) {
    const float*   point_feat = (const float*)d_in[0];
    const float*   point_xyz  = (const float*)d_in[1];
    const float*   sup_xyz    = (const float*)d_in[2];
    const int*     nidx       = (const int*)d_in[3];
    const void*    nmask      = d_in[4];
    const float*   init_feat  = (const float*)d_in[5];
    const float*   task_emb   = (const float*)d_in[6];
    const float*   W1 = (const float*)d_in[7];
    const float*   b1 = (const float*)d_in[8];
    const float*   W2 = (const float*)d_in[9];
    const float*   b2 = (const float*)d_in[10];
    const float*   Wf = (const float*)d_in[11];
    const float*   bf = (const float*)d_in[12];
    const float*   lng = (const float*)d_in[13];
    const float*   lnb = (const float*)d_in[14];
    float* out = (float*)d_out;

    cudaFuncSetAttribute(msg_kernel, cudaFuncAttributeMaxDynamicSharedMemorySize,
                         SMEM_BYTES);
    int sms = 148;
    cudaDeviceGetAttribute(&sms, cudaDevAttrMultiProcessorCount, 0);

    msg_kernel<<<sms, 512, SMEM_BYTES>>>(point_feat, point_xyz, sup_xyz,
                                         nidx, nmask, init_feat, task_emb,
                                         W1, b1, W2, b2, Wf, bf, lng, lnb, out);
}

// round 14
// speedup vs baseline: 1.2637x; 1.2637x over previous
#include <cuda_runtime.h>
#include <cuda_bf16.h>
#include <stdint.h>
#include <math.h>

// Problem constants
#define BB 8
#define NN 100000
#define MM 2048
#define KK 32
#define DD 128
#define IC 132
#define EPSV 1e-5f

// word strides (32-bit words; each word = 2 bf16 along K)
#define STRX 76
#define STRW1 76
#define STRW2 68

// smem word-offset layout
#define XS_W   0                 // 16 warps * 32 rows * 76 words = 38912
#define W1T_W  38912             // 128 * 76 = 9728
#define W2T_W  48640             // 128 * 68 = 8704
#define B1_W   57344             // 128
#define B2_W   57472             // 128
#define LNG_W  57600             // 128
#define LNB_W  57728             // 128
#define FLAG_W 57856             // 4
#define SMEM_WORDS 57860
#define SMEM_BYTES (SMEM_WORDS * 4)   // 231,440 B

#define XS_WARP_W 2432           // 32 * 76

// FiLM table in device global (L2-hot)
__device__ float g_film[BB * 2 * DD];

__device__ __forceinline__ float silu_f(float v) {
    return v * (1.0f / (1.0f + __expf(-v)));
}
__device__ __forceinline__ unsigned pkbf(float lo, float hi) {
    unsigned r;
    asm("cvt.rn.bf16x2.f32 %0, %1, %2;" : "=r"(r) : "f"(hi), "f"(lo));
    return r;
}
__device__ __forceinline__ void mma_bf16(float d[4],
                                         unsigned a0, unsigned a1,
                                         unsigned a2, unsigned a3,
                                         unsigned b0, unsigned b1) {
    asm volatile(
        "mma.sync.aligned.m16n8k16.row.col.f32.bf16.bf16.f32 "
        "{%0,%1,%2,%3}, {%4,%5,%6,%7}, {%8,%9}, {%0,%1,%2,%3};\n"
        : "+f"(d[0]), "+f"(d[1]), "+f"(d[2]), "+f"(d[3])
        : "r"(a0), "r"(a1), "r"(a2), "r"(a3), "r"(b0), "r"(b1));
}
__device__ __forceinline__ void ldsm4(unsigned& r0, unsigned& r1,
                                      unsigned& r2, unsigned& r3, unsigned a) {
    asm volatile("ldmatrix.sync.aligned.m8n8.x4.shared.b16 {%0,%1,%2,%3}, [%4];"
                 : "=r"(r0), "=r"(r1), "=r"(r2), "=r"(r3) : "r"(a));
}
__device__ __forceinline__ unsigned smem_u32(const void* p) {
    unsigned a;
    asm("{ .reg .u64 t; cvta.to.shared.u64 t, %1; cvt.u32.u64 %0, t; }"
        : "=r"(a) : "l"(p));
    return a;
}

// full gather (xyz + features) for one supernode into warp-private xs.
// Writes words 0..65 of rows < V (66..71 stay zero, 72..75 untouched).
// Feature batches of 8 rows (MLP=8) — latency-critical, do not reduce.
__device__ __forceinline__ void gather_su(unsigned* xsw,
                                          const float* __restrict__ point_feat,
                                          const float* __restrict__ point_xyz,
                                          const float* __restrict__ sup_xyz,
                                          int s, int b, unsigned bal, int V,
                                          int nid_k, int lane)
{
    const float* pf = point_feat + (size_t)b * NN * DD;
    // xyz: lane r handles row r (parallel across lanes)
    {
        const unsigned srcx = (lane < V) ? __fns(bal, 0, lane + 1) : 0u;
        const int nidx_l = __shfl_sync(0xffffffffu, nid_k, srcx);
        if (lane < V) {
            const float* px = point_xyz + (size_t)b * NN * 3;
            float rx  = px[nidx_l * 3 + 0] - sup_xyz[s * 3 + 0];
            float ryv = px[nidx_l * 3 + 1] - sup_xyz[s * 3 + 1];
            float rz  = px[nidx_l * 3 + 2] - sup_xyz[s * 3 + 2];
            float dd  = sqrtf(rx * rx + ryv * ryv + rz * rz);
            *(uint2*)(xsw + lane * STRX + 64) =
                make_uint2(pkbf(rx, ryv), pkbf(rz, dd));
        }
    }
    // features: batches of 8 rows, MLP=8
#pragma unroll
    for (int b8 = 0; b8 < 4; ++b8) {
        const int r0 = b8 * 8;
        if (r0 >= V) break;
        float4 f[8];
#pragma unroll
        for (int j = 0; j < 8; ++j) {
            const int r = r0 + j;
            const bool val = r < V;
            const unsigned src = val ? __fns(bal, 0, r + 1) : 0u;
            const int nid = __shfl_sync(0xffffffffu, nid_k, src);
            if (val)
                f[j] = *(const float4*)(pf + (size_t)nid * DD + 4 * lane);
        }
#pragma unroll
        for (int j = 0; j < 8; ++j) {
            const int r = r0 + j;
            if (r < V)
                *(uint2*)(xsw + r * STRX + 2 * lane) =
                    make_uint2(pkbf(f[j].x, f[j].y), pkbf(f[j].z, f[j].w));
        }
    }
    __syncwarp();
}

extern __shared__ unsigned usm[];

__global__ __launch_bounds__(512, 1)
void msg_kernel(const float* __restrict__ point_feat,
                const float* __restrict__ point_xyz,
                const float* __restrict__ sup_xyz,
                const int*   __restrict__ nidx,
                const void*  __restrict__ nmask,
                const float* __restrict__ init_feat,
                const float* __restrict__ task_emb,
                const float* __restrict__ W1, const float* __restrict__ b1,
                const float* __restrict__ W2, const float* __restrict__ b2,
                const float* __restrict__ Wf, const float* __restrict__ bf,
                const float* __restrict__ ln_g, const float* __restrict__ ln_b,
                float* __restrict__ out)
{
    float* b1s  = (float*)(usm + B1_W);
    float* b2s  = (float*)(usm + B2_W);
    float* lngs = (float*)(usm + LNG_W);
    float* lnbs = (float*)(usm + LNB_W);
    int*   flag = (int*)(usm + FLAG_W);

    const int tid = threadIdx.x;

    // ---- prologue: mask dtype detect ----
    if (tid == 0) *flag = 0;
    __syncthreads();
    {
        bool big = false;
        const unsigned* mw = (const unsigned*)nmask;
        for (int i = tid; i < 2048; i += 512)
            if (mw[i] > 1u) big = true;
        if (big) atomicOr(flag, 1);
    }
    // ---- FiLM table -> device global ----
    for (int p = 0; p < 4; ++p) {
        const int bb = p * 2 + (tid >> 8);
        const int j  = tid & 255;
        float acc = bf[j];
        const float* te = task_emb + bb * DD;
#pragma unroll 8
        for (int d = 0; d < DD; ++d)
            acc += te[d] * Wf[d * (2 * DD) + j];
        g_film[bb * 256 + j] = acc;
    }
    // ---- stage W1^T ----
    for (int i = tid; i < DD * STRW1; i += 512) {
        int col = i % DD, kw = i / DD;
        int k0 = 2 * kw, k1 = 2 * kw + 1;
        float v0 = (k0 < IC) ? W1[k0 * DD + col] : 0.f;
        float v1 = (k1 < IC) ? W1[k1 * DD + col] : 0.f;
        usm[W1T_W + col * STRW1 + kw] = pkbf(v0, v1);
    }
    // ---- stage W2^T ----
    for (int i = tid; i < DD * STRW2; i += 512) {
        int col = i % DD, kw = i / DD;
        int k0 = 2 * kw, k1 = 2 * kw + 1;
        float v0 = (k0 < DD) ? W2[k0 * DD + col] : 0.f;
        float v1 = (k1 < DD) ? W2[k1 * DD + col] : 0.f;
        usm[W2T_W + col * STRW2 + kw] = pkbf(v0, v1);
    }
    // ---- zero xs pad words 66..71 (k 132..143) ----
    for (int i = tid; i < 16 * 32 * 6; i += 512) {
        int w_ = i / 192, rem = i % 192;
        int row = rem / 6, pw = 66 + rem % 6;
        usm[XS_W + w_ * XS_WARP_W + row * STRX + pw] = 0u;
    }
    // ---- small vectors ----
    for (int i = tid; i < DD; i += 512) {
        b1s[i] = b1[i]; b2s[i] = b2[i]; lngs[i] = ln_g[i]; lnbs[i] = ln_b[i];
    }
    __syncthreads();
    const int mask_u8 = *flag;

    const int wid  = tid >> 5;
    const int lane = tid & 31;
    const int q    = lane & 3;
    const int g    = lane >> 2;

    unsigned* xsw = usm + XS_W + wid * XS_WARP_W;

    const unsigned sbase = smem_u32(usm);
    const int rowA = lane & 15, halfA = lane >> 4;
    const unsigned axA0 = sbase + 4u * (XS_W + wid * XS_WARP_W + rowA * STRX + halfA * 4);
    const int rB = lane & 7, tB = (lane >> 4) & 1, hB = (lane >> 3) & 1;
    const unsigned awB1 = sbase + 4u * (W1T_W + (tB * 8 + rB) * STRW1 + hB * 4);
    const unsigned awB2 = sbase + 4u * (W2T_W + (tB * 8 + rB) * STRW2 + hB * 4);

    const int TOT = BB * MM;
    const int sstep = gridDim.x * 16;

    int s = blockIdx.x * 16 + wid;
    unsigned bal = 0; int V = 0;

    // ---- software-pipeline prologue: gather first supernode ----
    if (s < TOT) {
        const size_t kb = (size_t)s * KK + lane;
        const int nid_k = nidx[kb];
        bool mk;
        if (mask_u8) mk = ((const uint8_t*)nmask)[kb] != 0;
        else         mk = ((const int*)nmask)[kb] != 0;
        bal = __ballot_sync(0xffffffffu, mk);
        V = __popc(bal);
        gather_su(xsw, point_feat, point_xyz, sup_xyz, s, s >> 11, bal, V,
                  nid_k, lane);
    }

    for (; s < TOT; s += sstep) {
        const int b = s >> 11;
        const int sn = s + sstep;
        const bool have = sn < TOT;

        // prefetch next supernode's indices + mask
        int nidk_n = 0; bool mk_n = false;
        if (have) {
            const size_t kbn = (size_t)sn * KK + lane;
            nidk_n = nidx[kbn];
            if (mask_u8) mk_n = ((const uint8_t*)nmask)[kbn] != 0;
            else         mk_n = ((const int*)nmask)[kbn] != 0;
        }

        // ---- GEMM1 over tiles -> masked f32 hidden row-sums (R12 schedule) ----
        float hs[4][4][2];
#pragma unroll
        for (int nb = 0; nb < 4; ++nb)
#pragma unroll
            for (int t = 0; t < 4; ++t)
                hs[nb][t][0] = hs[nb][t][1] = 0.f;

        const int ntl = (V > 16) ? 2 : 1;
        for (int tl = 0; tl < ntl; ++tl) {
            const bool v0 = (tl * 16 + g)     < V;
            const bool v1 = (tl * 16 + g + 8) < V;
#pragma unroll
            for (int nb = 0; nb < 4; ++nb) {
                float acc[4][4];
#pragma unroll
                for (int t = 0; t < 4; ++t)
                    acc[t][0] = acc[t][1] = acc[t][2] = acc[t][3] = 0.f;
                unsigned aA = axA0 + (unsigned)tl * 4864u;   // +16*STRX*4
                unsigned aB = awB1 + nb * 9728u;             // +32*STRW1*4
#pragma unroll
                for (int kk = 0; kk < 9; ++kk) {
                    unsigned A0, A1, A2, A3, B0, B1, B2, B3, B4, B5, B6, B7;
                    ldsm4(A0, A1, A2, A3, aA);
                    ldsm4(B0, B1, B2, B3, aB);
                    ldsm4(B4, B5, B6, B7, aB + 4864u);       // +16*STRW1*4
                    mma_bf16(acc[0], A0, A1, A2, A3, B0, B1);
                    mma_bf16(acc[1], A0, A1, A2, A3, B2, B3);
                    mma_bf16(acc[2], A0, A1, A2, A3, B4, B5);
                    mma_bf16(acc[3], A0, A1, A2, A3, B6, B7);
                    aA += 32u; aB += 32u;
                }
                // bias + f32 silu + masked accumulate into row-sum
#pragma unroll
                for (int t = 0; t < 4; ++t) {
                    float2 bv = *(const float2*)(b1s + nb * 32 + t * 8 + 2 * q);
                    float s0 = silu_f(acc[t][0] + bv.x);
                    float s1 = silu_f(acc[t][1] + bv.y);
                    float s2 = silu_f(acc[t][2] + bv.x);
                    float s3 = silu_f(acc[t][3] + bv.y);
                    hs[nb][t][0] += (v0 ? s0 : 0.f) + (v1 ? s2 : 0.f);
                    hs[nb][t][1] += (v0 ? s1 : 0.f) + (v1 ? s3 : 0.f);
                }
            }
        }
        // butterfly reduce over g-lanes (once per supernode)
#pragma unroll
        for (int nb = 0; nb < 4; ++nb)
#pragma unroll
            for (int t = 0; t < 4; ++t) {
#pragma unroll
                for (int off = 4; off <= 16; off <<= 1) {
                    hs[nb][t][0] += __shfl_xor_sync(0xffffffffu, hs[nb][t][0], off);
                    hs[nb][t][1] += __shfl_xor_sync(0xffffffffu, hs[nb][t][1], off);
                }
            }
        // pack hsum -> bf16x2 A-fragments; zero for non-g0 lanes ONCE
        // (removes per-mma selects inside GEMM2)
        const bool g0 = (g == 0);
        unsigned hpk[4][4];
#pragma unroll
        for (int nb = 0; nb < 4; ++nb)
#pragma unroll
            for (int t = 0; t < 4; ++t)
                hpk[nb][t] = g0 ? pkbf(hs[nb][t][0], hs[nb][t][1]) : 0u;

        // ---- xs k-words now dead: gather next supernode (hidden by GEMM2) ----
        unsigned bal_n = 0; int V_n = 0;
        if (have) {
            bal_n = __ballot_sync(0xffffffffu, mk_n);
            V_n = __popc(bal_n);
            gather_su(xsw, point_feat, point_xyz, sup_xyz, sn, sn >> 11,
                      bal_n, V_n, nidk_n, lane);
        }
        // prefetch epilogue residual input (covered by GEMM2, short live range)
        float4 fi = *(const float4*)(init_feat + (size_t)s * DD + 4 * lane);

        // ---- GEMM2: msg_sum = hsum @ W2, single m16 tile, row 0 only ----
        for (int nb2 = 0; nb2 < 4; ++nb2) {
            float facc[4][4];
#pragma unroll
            for (int t = 0; t < 4; ++t)
                facc[t][0] = facc[t][1] = facc[t][2] = facc[t][3] = 0.f;
            unsigned aB = awB2 + nb2 * 8704u;                // +32*STRW2*4
#pragma unroll
            for (int kk = 0; kk < 8; ++kk) {
                unsigned B0, B1, B2, B3, B4, B5, B6, B7;
                ldsm4(B0, B1, B2, B3, aB);
                ldsm4(B4, B5, B6, B7, aB + 4352u);           // +16*STRW2*4
                const unsigned a0 = hpk[kk >> 1][2 * (kk & 1)];
                const unsigned a2 = hpk[kk >> 1][2 * (kk & 1) + 1];
                mma_bf16(facc[0], a0, 0u, a2, 0u, B0, B1);
                mma_bf16(facc[1], a0, 0u, a2, 0u, B2, B3);
                mma_bf16(facc[2], a0, 0u, a2, 0u, B4, B5);
                mma_bf16(facc[3], a0, 0u, a2, 0u, B6, B7);
                aB += 32u;
            }
            // row 0 of D = msg_sum, held by lanes g==0 — no reduce needed
            if (lane < 4) {
#pragma unroll
                for (int t = 0; t < 4; ++t) {
                    const int c = nb2 * 32 + t * 8 + 2 * q;
                    *(float2*)(xsw + (c >> 2) * STRX + 72 + (c & 3)) =
                        make_float2(facc[t][0], facc[t][1]);
                }
            }
        }
        __syncwarp();

        // ---- epilogue: mean(+V*b2), FiLM, residual, LayerNorm ----
        {
            float4 msg = *(float4*)(xsw + lane * STRX + 72);
            const float Vf = (float)V;
            const float invV = 1.0f / fmaxf(Vf, 1.0f);
            float4 b2v = *(const float4*)(b2s + 4 * lane);
            float4 gm  = *(const float4*)(g_film + b * 256 + 4 * lane);
            float4 bt  = *(const float4*)(g_film + b * 256 + 128 + 4 * lane);
            float h0 = fi.x + ((msg.x + Vf * b2v.x) * invV) * (1.0f + gm.x) + bt.x;
            float h1 = fi.y + ((msg.y + Vf * b2v.y) * invV) * (1.0f + gm.y) + bt.y;
            float h2 = fi.z + ((msg.z + Vf * b2v.z) * invV) * (1.0f + gm.z) + bt.z;
            float h3 = fi.w + ((msg.w + Vf * b2v.w) * invV) * (1.0f + gm.w) + bt.w;
            float sum = h0 + h1 + h2 + h3;
            float sq  = h0 * h0 + h1 * h1 + h2 * h2 + h3 * h3;
#pragma unroll
            for (int off = 16; off; off >>= 1) {
                sum += __shfl_xor_sync(0xffffffffu, sum, off);
                sq  += __shfl_xor_sync(0xffffffffu, sq,  off);
            }
            const float mu  = sum * (1.0f / DD);
            const float var = sq * (1.0f / DD) - mu * mu;
            const float rs  = rsqrtf(var + EPSV);
            float4 lg = *(const float4*)(lngs + 4 * lane);
            float4 lb = *(const float4*)(lnbs + 4 * lane);
            float4 y;
            y.x = (h0 - mu) * rs * lg.x + lb.x;
            y.y = (h1 - mu) * rs * lg.y + lb.y;
            y.z = (h2 - mu) * rs * lg.z + lb.z;
            y.w = (h3 - mu) * rs * lg.w + lb.w;
            *(float4*)(out + (size_t)s * DD + 4 * lane) = y;
        }

        // rotate pipeline state
        bal = bal_n; V = V_n;
    }
}

// ---------------------------------------------------------------------------
extern "C" void kernel_launch(void* const* d_in, const int* in_sizes, int n_in,
                              void* d_out, int out_size) {
    const float*   point_feat = (const float*)d_in[0];
    const float*   point_xyz  = (const float*)d_in[1];
    const float*   sup_xyz    = (const float*)d_in[2];
    const int*     nidx       = (const int*)d_in[3];
    const void*    nmask      = d_in[4];
    const float*   init_feat  = (const float*)d_in[5];
    const float*   task_emb   = (const float*)d_in[6];
    const float*   W1 = (const float*)d_in[7];
    const float*   b1 = (const float*)d_in[8];
    const float*   W2 = (const float*)d_in[9];
    const float*   b2 = (const float*)d_in[10];
    const float*   Wf = (const float*)d_in[11];
    const float*   bf = (const float*)d_in[12];
    const float*   lng = (const float*)d_in[13];
    const float*   lnb = (const float*)d_in[14];
    float* out = (float*)d_out;

    cudaFuncSetAttribute(msg_kernel, cudaFuncAttributeMaxDynamicSharedMemorySize,
                         SMEM_BYTES);
    int sms = 148;
    cudaDeviceGetAttribute(&sms, cudaDevAttrMultiProcessorCount, 0);

    msg_kernel<<<sms, 512, SMEM_BYTES>>>(point_feat, point_xyz, sup_xyz,
                                         nidx, nmask, init_feat, task_emb,
                                         W1, b1, W2, b2, Wf, bf, lng, lnb, out);
}